// round 1
// baseline (speedup 1.0000x reference)
#include <cuda_runtime.h>

// Ax[b,m,t] = sum_{c=0..7} x[b, m*8+c, t] * W[m,c]
// x: (16, 1024, 2048) f32, W: (128, 8) f32
// out layout: Ax (16*128*2048 floats) then A_full (128*1024 floats)

#define B_ 16
#define M_ 128
#define C_ 8
#define T_ 2048
#define T4_ (T_ / 4)          // 512 float4 per row
#define AX_ELEMS (B_ * M_ * T_)        // 4194304
#define AX_VEC   (AX_ELEMS / 4)        // 1048576

__global__ void __launch_bounds__(256)
ax_kernel(const float* __restrict__ x, const float* __restrict__ W,
          float* __restrict__ out)
{
    int idx = blockIdx.x * blockDim.x + threadIdx.x;   // one float4 of Ax
    if (idx >= AX_VEC) return;

    int t4 = idx & (T4_ - 1);          // 0..511
    int m  = (idx >> 9) & (M_ - 1);    // 0..127
    int b  = idx >> 16;                // 0..15

    // base element offset of x[b, m*8, t4*4]
    const float4* xb = (const float4*)(x + ((size_t)(b * 1024 + m * C_) * T_)) + t4;
    const float*  w  = W + m * C_;     // uniform within warp -> broadcast

    float4 acc;
    {
        float4 v = xb[0];
        float wc = w[0];
        acc.x = v.x * wc; acc.y = v.y * wc; acc.z = v.z * wc; acc.w = v.w * wc;
    }
#pragma unroll
    for (int c = 1; c < C_; ++c) {
        float4 v = xb[(size_t)c * T4_];
        float wc = w[c];
        acc.x = fmaf(v.x, wc, acc.x);
        acc.y = fmaf(v.y, wc, acc.y);
        acc.z = fmaf(v.z, wc, acc.z);
        acc.w = fmaf(v.w, wc, acc.w);
    }

    ((float4*)out)[idx] = acc;
}

// A_full[i, j] = (j>>3 == i) ? W[i, j&7] : 0, shape (128, 1024)
__global__ void __launch_bounds__(256)
afull_kernel(const float* __restrict__ W, float* __restrict__ out)
{
    int idx = blockIdx.x * blockDim.x + threadIdx.x;   // 0 .. 128*1024-1
    if (idx >= M_ * 1024) return;
    int row = idx >> 10;
    int col = idx & 1023;
    float v = ((col >> 3) == row) ? W[row * C_ + (col & 7)] : 0.0f;
    out[AX_ELEMS + idx] = v;
}

extern "C" void kernel_launch(void* const* d_in, const int* in_sizes, int n_in,
                              void* d_out, int out_size)
{
    const float* x = (const float*)d_in[0];
    const float* W = (const float*)d_in[1];
    float* out = (float*)d_out;

    ax_kernel<<<AX_VEC / 256, 256>>>(x, W, out);
    afull_kernel<<<(M_ * 1024) / 256, 256>>>(W, out);
}

// round 2
// speedup vs baseline: 1.1055x; 1.1055x over previous
#include <cuda_runtime.h>

// Ax[b,m,t] = sum_{c=0..7} x[b, m*8+c, t] * W[m,c]
// x: (16, 1024, 2048) f32, W: (128, 8) f32
// out layout: Ax (16*128*2048 floats) then A_full (128*1024 floats), fused in one kernel.

#define B_ 16
#define M_ 128
#define C_ 8
#define T_ 2048
#define T4_ (T_ / 4)                  // 512 float4 per channel row
#define AX_ELEMS (B_ * M_ * T_)       // 4194304
#define AX_VEC   (AX_ELEMS / 4)       // 1048576 float4
#define AX_BLOCKS (AX_VEC / 256)      // 4096
#define AF_ELEMS (M_ * 1024)          // 131072
#define AF_VEC   (AF_ELEMS / 4)       // 32768 float4
#define AF_BLOCKS (AF_VEC / 256)      // 128

__global__ void __launch_bounds__(256)
fused_kernel(const float* __restrict__ x, const float* __restrict__ W,
             float* __restrict__ out)
{
    int bid = blockIdx.x;

    if (bid < AX_BLOCKS) {
        // ---- Ax path: one float4 of Ax per thread ----
        int idx = bid * 256 + threadIdx.x;
        int t4 = idx & (T4_ - 1);          // 0..511
        int m  = (idx >> 9) & (M_ - 1);    // 0..127
        int b  = idx >> 16;                // 0..15

        const float4* xb = (const float4*)(x + ((size_t)(b * 1024 + m * C_) * T_)) + t4;
        const float*  w  = W + m * C_;     // uniform within warp -> L1 broadcast

        float4 acc;
        {
            float4 v = __ldcs(&xb[0]);
            float wc = w[0];
            acc.x = v.x * wc; acc.y = v.y * wc; acc.z = v.z * wc; acc.w = v.w * wc;
        }
#pragma unroll
        for (int c = 1; c < C_; ++c) {
            float4 v = __ldcs(&xb[(size_t)c * T4_]);
            float wc = w[c];
            acc.x = fmaf(v.x, wc, acc.x);
            acc.y = fmaf(v.y, wc, acc.y);
            acc.z = fmaf(v.z, wc, acc.z);
            acc.w = fmaf(v.w, wc, acc.w);
        }
        ((float4*)out)[idx] = acc;
    } else {
        // ---- A_full tail: one float4 of A_full per thread ----
        int idx = (bid - AX_BLOCKS) * 256 + threadIdx.x;   // 0..AF_VEC-1
        int row  = idx >> 8;                // 1024 cols = 256 float4 per row
        int col4 = idx & 255;
        int col0 = col4 * 4;

        float4 v;
        float* vp = &v.x;
#pragma unroll
        for (int j = 0; j < 4; ++j) {
            int col = col0 + j;
            vp[j] = ((col >> 3) == row) ? W[row * C_ + (col & 7)] : 0.0f;
        }
        ((float4*)(out + AX_ELEMS))[idx] = v;
    }
}

extern "C" void kernel_launch(void* const* d_in, const int* in_sizes, int n_in,
                              void* d_out, int out_size)
{
    const float* x = (const float*)d_in[0];
    const float* W = (const float*)d_in[1];
    float* out = (float*)d_out;

    fused_kernel<<<AX_BLOCKS + AF_BLOCKS, 256>>>(x, W, out);
}

// round 3
// speedup vs baseline: 1.1515x; 1.0417x over previous
#include <cuda_runtime.h>

// Ax[b,m,t] = sum_{c=0..7} x[b, m*8+c, t] * W[m,c]
// x: (16, 1024, 2048) f32, W: (128, 8) f32
// out layout: Ax (16*128*2048 floats) then A_full (128*1024 floats).
// Persistent grid-stride kernel: Ax vec range [0, AX_VEC), A_full vec range
// [AX_VEC, AX_VEC + AF_VEC).

#define B_ 16
#define M_ 128
#define C_ 8
#define T_ 2048
#define T4_ (T_ / 4)                  // 512 float4 per channel row
#define AX_ELEMS (B_ * M_ * T_)       // 4194304
#define AX_VEC   (AX_ELEMS / 4)       // 1048576 float4
#define AF_ELEMS (M_ * 1024)          // 131072
#define AF_VEC   (AF_ELEMS / 4)       // 32768 float4
#define TOTAL_VEC (AX_VEC + AF_VEC)   // 1081344

#define NBLOCKS 1184                  // 148 SMs * 8 resident blocks
#define NTHREADS 256

__global__ void __launch_bounds__(NTHREADS)
fused_kernel(const float* __restrict__ x, const float* __restrict__ W,
             float* __restrict__ out)
{
    const int stride = NBLOCKS * NTHREADS;

    for (int idx = blockIdx.x * NTHREADS + threadIdx.x; idx < TOTAL_VEC; idx += stride) {
        if (idx < AX_VEC) {
            // ---- Ax path: one float4 of Ax ----
            int t4 = idx & (T4_ - 1);          // 0..511
            int m  = (idx >> 9) & (M_ - 1);    // 0..127
            int b  = idx >> 16;                // 0..15

            const float4* xb = (const float4*)(x + ((size_t)(b * 1024 + m * C_) * T_)) + t4;
            const float*  w  = W + m * C_;     // uniform within warp -> L1 broadcast

            // front-batch all 8 loads for MLP
            float4 v0 = __ldcs(&xb[0 * T4_]);
            float4 v1 = __ldcs(&xb[1 * T4_]);
            float4 v2 = __ldcs(&xb[2 * T4_]);
            float4 v3 = __ldcs(&xb[3 * T4_]);
            float4 v4 = __ldcs(&xb[4 * T4_]);
            float4 v5 = __ldcs(&xb[5 * T4_]);
            float4 v6 = __ldcs(&xb[6 * T4_]);
            float4 v7 = __ldcs(&xb[7 * T4_]);

            float w0 = w[0], w1 = w[1], w2 = w[2], w3 = w[3];
            float w4 = w[4], w5 = w[5], w6 = w[6], w7 = w[7];

            float4 acc;
            acc.x = v0.x * w0; acc.y = v0.y * w0; acc.z = v0.z * w0; acc.w = v0.w * w0;
            acc.x = fmaf(v1.x, w1, acc.x); acc.y = fmaf(v1.y, w1, acc.y);
            acc.z = fmaf(v1.z, w1, acc.z); acc.w = fmaf(v1.w, w1, acc.w);
            acc.x = fmaf(v2.x, w2, acc.x); acc.y = fmaf(v2.y, w2, acc.y);
            acc.z = fmaf(v2.z, w2, acc.z); acc.w = fmaf(v2.w, w2, acc.w);
            acc.x = fmaf(v3.x, w3, acc.x); acc.y = fmaf(v3.y, w3, acc.y);
            acc.z = fmaf(v3.z, w3, acc.z); acc.w = fmaf(v3.w, w3, acc.w);
            acc.x = fmaf(v4.x, w4, acc.x); acc.y = fmaf(v4.y, w4, acc.y);
            acc.z = fmaf(v4.z, w4, acc.z); acc.w = fmaf(v4.w, w4, acc.w);
            acc.x = fmaf(v5.x, w5, acc.x); acc.y = fmaf(v5.y, w5, acc.y);
            acc.z = fmaf(v5.z, w5, acc.z); acc.w = fmaf(v5.w, w5, acc.w);
            acc.x = fmaf(v6.x, w6, acc.x); acc.y = fmaf(v6.y, w6, acc.y);
            acc.z = fmaf(v6.z, w6, acc.z); acc.w = fmaf(v6.w, w6, acc.w);
            acc.x = fmaf(v7.x, w7, acc.x); acc.y = fmaf(v7.y, w7, acc.y);
            acc.z = fmaf(v7.z, w7, acc.z); acc.w = fmaf(v7.w, w7, acc.w);

            __stcs(&((float4*)out)[idx], acc);
        } else {
            // ---- A_full: one float4 ----
            int aidx = idx - AX_VEC;            // 0..AF_VEC-1
            int row  = aidx >> 8;               // 256 float4 per 1024-col row
            int col0 = (aidx & 255) * 4;

            float4 v;
            float* vp = &v.x;
#pragma unroll
            for (int j = 0; j < 4; ++j) {
                int col = col0 + j;
                vp[j] = ((col >> 3) == row) ? W[row * C_ + (col & 7)] : 0.0f;
            }
            __stcs(&((float4*)(out + AX_ELEMS))[aidx], v);
        }
    }
}

extern "C" void kernel_launch(void* const* d_in, const int* in_sizes, int n_in,
                              void* d_out, int out_size)
{
    const float* x = (const float*)d_in[0];
    const float* W = (const float*)d_in[1];
    float* out = (float*)d_out;

    fused_kernel<<<NBLOCKS, NTHREADS>>>(x, W, out);
}